// round 1
// baseline (speedup 1.0000x reference)
#include <cuda_runtime.h>
#include <cstdint>
#include <math.h>

// Problem dims
#define Bb 8
#define Tt 4096
#define Cc 512
#define NCHUNK 64
#define LCHUNK 64   // Tt / NCHUNK

// Scratch (device globals: no runtime allocation allowed)
__device__ float g_y[Bb * Tt * Cc];          // 64 MB intermediate y
__device__ float g_A[Bb * NCHUNK * Cc];      // per-chunk weighted sums

// ---------------------------------------------------------------------------
// Kernel 1: per-chunk absolutely-weighted sums  A[b,k,c] = sum_j d^(t0+j) x
// ---------------------------------------------------------------------------
__global__ void __launch_bounds__(128) chunk_sum_kernel(
    const float* __restrict__ x, const float* __restrict__ logd)
{
    const int b = blockIdx.x / NCHUNK;
    const int k = blockIdx.x % NCHUNK;
    const int c = threadIdx.x * 4;

    float4 ld4 = *reinterpret_cast<const float4*>(logd + c);
    const float d0 = 1.0f / (1.0f + expf(-ld4.x));
    const float d1 = 1.0f / (1.0f + expf(-ld4.y));
    const float d2 = 1.0f / (1.0f + expf(-ld4.z));
    const float d3 = 1.0f / (1.0f + expf(-ld4.w));

    const float ft0 = (float)(k * LCHUNK);
    float w0 = exp2f(ft0 * log2f(d0));
    float w1 = exp2f(ft0 * log2f(d1));
    float w2 = exp2f(ft0 * log2f(d2));
    float w3 = exp2f(ft0 * log2f(d3));

    const float* xp = x + ((size_t)b * Tt + (size_t)k * LCHUNK) * Cc + c;

    float a0 = 0.f, a1 = 0.f, a2 = 0.f, a3 = 0.f;
#pragma unroll 8
    for (int j = 0; j < LCHUNK; ++j) {
        float4 v = *reinterpret_cast<const float4*>(xp + (size_t)j * Cc);
        a0 += w0 * v.x;
        a1 += w1 * v.y;
        a2 += w2 * v.z;
        a3 += w3 * v.w;
        w0 *= d0; w1 *= d1; w2 *= d2; w3 *= d3;
    }

    float4 r; r.x = a0; r.y = a1; r.z = a2; r.w = a3;
    *reinterpret_cast<float4*>(&g_A[((size_t)b * NCHUNK + k) * Cc + c]) = r;
}

// ---------------------------------------------------------------------------
// Kernel 2: prefix over chunks + local rescan; y = d^(T-1-t) * S
// ---------------------------------------------------------------------------
__global__ void __launch_bounds__(128) apply_kernel(
    const float* __restrict__ x, const float* __restrict__ logd)
{
    const int b = blockIdx.x / NCHUNK;
    const int k = blockIdx.x % NCHUNK;
    const int c = threadIdx.x * 4;

    float4 ld4 = *reinterpret_cast<const float4*>(logd + c);
    const float d0 = 1.0f / (1.0f + expf(-ld4.x));
    const float d1 = 1.0f / (1.0f + expf(-ld4.y));
    const float d2 = 1.0f / (1.0f + expf(-ld4.z));
    const float d3 = 1.0f / (1.0f + expf(-ld4.w));
    const float l20 = log2f(d0), l21 = log2f(d1), l22 = log2f(d2), l23 = log2f(d3);

    // Prefix of earlier chunk sums
    float P0 = 0.f, P1 = 0.f, P2 = 0.f, P3 = 0.f;
    const float* Aprow = g_A + (size_t)b * NCHUNK * Cc + c;
    for (int kk = 0; kk < k; ++kk) {
        float4 v = *reinterpret_cast<const float4*>(Aprow + (size_t)kk * Cc);
        P0 += v.x; P1 += v.y; P2 += v.z; P3 += v.w;
    }

    const int t0 = k * LCHUNK;
    const float ft0 = (float)t0;
    float w0 = exp2f(ft0 * l20);
    float w1 = exp2f(ft0 * l21);
    float w2 = exp2f(ft0 * l22);
    float w3 = exp2f(ft0 * l23);

    // p_t = d^(T-1-t): grows with t. Iterating pt *= 1/d from an underflowed 0
    // would stick at 0, so chunks where p_t transitions out of underflow use
    // exact exp2f per step ("exact" mode). Elsewhere iterate (<=63 ulp drift).
    const float eb0 = (float)(Tt - 1 - t0) * l20;                 // log2(pt) at j=0
    const float eb1 = (float)(Tt - 1 - t0) * l21;
    const float eb2 = (float)(Tt - 1 - t0) * l22;
    const float eb3 = (float)(Tt - 1 - t0) * l23;
    const float ee0 = (float)(Tt - 1 - t0 - (LCHUNK - 1)) * l20;  // log2(pt) at j=L-1
    const float ee1 = (float)(Tt - 1 - t0 - (LCHUNK - 1)) * l21;
    const float ee2 = (float)(Tt - 1 - t0 - (LCHUNK - 1)) * l22;
    const float ee3 = (float)(Tt - 1 - t0 - (LCHUNK - 1)) * l23;
    const bool ex0 = (eb0 < -100.f) && (ee0 > -140.f);
    const bool ex1 = (eb1 < -100.f) && (ee1 > -140.f);
    const bool ex2 = (eb2 < -100.f) && (ee2 > -140.f);
    const bool ex3 = (eb3 < -100.f) && (ee3 > -140.f);
    const bool anyex = ex0 | ex1 | ex2 | ex3;

    float pt0 = exp2f(eb0), pt1 = exp2f(eb1), pt2 = exp2f(eb2), pt3 = exp2f(eb3);
    const float i0 = 1.0f / d0, i1 = 1.0f / d1, i2 = 1.0f / d2, i3 = 1.0f / d3;

    float S0 = P0, S1 = P1, S2 = P2, S3 = P3;

    const float* xp = x + ((size_t)b * Tt + t0) * Cc + c;
    float* yp = g_y + ((size_t)b * Tt + t0) * Cc + c;

    if (!anyex) {
#pragma unroll 4
        for (int j = 0; j < LCHUNK; ++j) {
            float4 v = *reinterpret_cast<const float4*>(xp + (size_t)j * Cc);
            S0 += w0 * v.x; w0 *= d0;
            S1 += w1 * v.y; w1 *= d1;
            S2 += w2 * v.z; w2 *= d2;
            S3 += w3 * v.w; w3 *= d3;
            float4 r;
            r.x = pt0 * S0; r.y = pt1 * S1; r.z = pt2 * S2; r.w = pt3 * S3;
            pt0 *= i0; pt1 *= i1; pt2 *= i2; pt3 *= i3;
            *reinterpret_cast<float4*>(yp + (size_t)j * Cc) = r;
        }
    } else {
        for (int j = 0; j < LCHUNK; ++j) {
            const float tj = (float)(Tt - 1 - t0 - j);
            pt0 = ex0 ? exp2f(tj * l20) : pt0;
            pt1 = ex1 ? exp2f(tj * l21) : pt1;
            pt2 = ex2 ? exp2f(tj * l22) : pt2;
            pt3 = ex3 ? exp2f(tj * l23) : pt3;
            float4 v = *reinterpret_cast<const float4*>(xp + (size_t)j * Cc);
            S0 += w0 * v.x; w0 *= d0;
            S1 += w1 * v.y; w1 *= d1;
            S2 += w2 * v.z; w2 *= d2;
            S3 += w3 * v.w; w3 *= d3;
            float4 r;
            r.x = pt0 * S0; r.y = pt1 * S1; r.z = pt2 * S2; r.w = pt3 * S3;
            pt0 = ex0 ? pt0 : pt0 * i0;
            pt1 = ex1 ? pt1 : pt1 * i1;
            pt2 = ex2 ? pt2 : pt2 * i2;
            pt3 = ex3 ? pt3 : pt3 * i3;
            *reinterpret_cast<float4*>(yp + (size_t)j * Cc) = r;
        }
    }
}

// ---------------------------------------------------------------------------
// Kernel 3: out[m,n] = sum_k y[m,k] * W[n,k] + bias[n]
// M=32768, N=512, K=512. 128x128x8 tiles, 256 threads, 8x8 per thread,
// double-buffered SMEM, register prefetch.
// ---------------------------------------------------------------------------
#define BM 128
#define BN 128
#define BKq 8

__global__ void __launch_bounds__(256, 2) gemm_kernel(
    const float* __restrict__ W, const float* __restrict__ bias,
    float* __restrict__ out)
{
    __shared__ float As[2][BKq][BM];
    __shared__ float Bs[2][BKq][BN];

    const int tid = threadIdx.x;
    const int bm = blockIdx.y, bn = blockIdx.x;
    const int lrow = tid >> 1;
    const int lcol = (tid & 1) << 2;

    const float* Ap = g_y + ((size_t)(bm * BM + lrow)) * Cc + lcol;
    const float* Bp = W + ((size_t)(bn * BN + lrow)) * Cc + lcol;

    const int tx = tid & 15;
    const int ty = tid >> 4;

    float acc[8][8];
#pragma unroll
    for (int i = 0; i < 8; ++i)
#pragma unroll
        for (int j = 0; j < 8; ++j) acc[i][j] = 0.f;

    // Preload tile 0
    {
        float4 a = *reinterpret_cast<const float4*>(Ap);
        float4 bv = *reinterpret_cast<const float4*>(Bp);
        As[0][lcol + 0][lrow] = a.x; As[0][lcol + 1][lrow] = a.y;
        As[0][lcol + 2][lrow] = a.z; As[0][lcol + 3][lrow] = a.w;
        Bs[0][lcol + 0][lrow] = bv.x; Bs[0][lcol + 1][lrow] = bv.y;
        Bs[0][lcol + 2][lrow] = bv.z; Bs[0][lcol + 3][lrow] = bv.w;
    }
    __syncthreads();

    int buf = 0;
    const int KT = Cc / BKq;  // 64
    for (int kt = 1; kt <= KT; ++kt) {
        float4 an, bnv;
        if (kt < KT) {
            an  = *reinterpret_cast<const float4*>(Ap + kt * BKq);
            bnv = *reinterpret_cast<const float4*>(Bp + kt * BKq);
        }
#pragma unroll
        for (int kk = 0; kk < BKq; ++kk) {
            float4 a0 = *reinterpret_cast<const float4*>(&As[buf][kk][ty * 8]);
            float4 a1 = *reinterpret_cast<const float4*>(&As[buf][kk][ty * 8 + 4]);
            float4 b0 = *reinterpret_cast<const float4*>(&Bs[buf][kk][tx * 8]);
            float4 b1 = *reinterpret_cast<const float4*>(&Bs[buf][kk][tx * 8 + 4]);
            float ar[8] = {a0.x, a0.y, a0.z, a0.w, a1.x, a1.y, a1.z, a1.w};
            float br[8] = {b0.x, b0.y, b0.z, b0.w, b1.x, b1.y, b1.z, b1.w};
#pragma unroll
            for (int i = 0; i < 8; ++i)
#pragma unroll
                for (int j = 0; j < 8; ++j)
                    acc[i][j] += ar[i] * br[j];
        }
        if (kt < KT) {
            As[buf ^ 1][lcol + 0][lrow] = an.x; As[buf ^ 1][lcol + 1][lrow] = an.y;
            As[buf ^ 1][lcol + 2][lrow] = an.z; As[buf ^ 1][lcol + 3][lrow] = an.w;
            Bs[buf ^ 1][lcol + 0][lrow] = bnv.x; Bs[buf ^ 1][lcol + 1][lrow] = bnv.y;
            Bs[buf ^ 1][lcol + 2][lrow] = bnv.z; Bs[buf ^ 1][lcol + 3][lrow] = bnv.w;
            __syncthreads();
            buf ^= 1;
        }
    }

    // Epilogue: add bias, store
    float4 bb0 = *reinterpret_cast<const float4*>(bias + bn * BN + tx * 8);
    float4 bb1 = *reinterpret_cast<const float4*>(bias + bn * BN + tx * 8 + 4);
#pragma unroll
    for (int i = 0; i < 8; ++i) {
        size_t row = (size_t)bm * BM + ty * 8 + i;
        float* op = out + row * Cc + bn * BN + tx * 8;
        float4 r0, r1;
        r0.x = acc[i][0] + bb0.x; r0.y = acc[i][1] + bb0.y;
        r0.z = acc[i][2] + bb0.z; r0.w = acc[i][3] + bb0.w;
        r1.x = acc[i][4] + bb1.x; r1.y = acc[i][5] + bb1.y;
        r1.z = acc[i][6] + bb1.z; r1.w = acc[i][7] + bb1.w;
        *reinterpret_cast<float4*>(op) = r0;
        *reinterpret_cast<float4*>(op + 4) = r1;
    }
}

// ---------------------------------------------------------------------------
extern "C" void kernel_launch(void* const* d_in, const int* in_sizes, int n_in,
                              void* d_out, int out_size)
{
    (void)in_sizes; (void)n_in; (void)out_size;
    const float* x    = (const float*)d_in[0];
    const float* logd = (const float*)d_in[1];
    const float* mixw = (const float*)d_in[2];
    const float* bias = (const float*)d_in[3];
    float* out = (float*)d_out;

    chunk_sum_kernel<<<Bb * NCHUNK, 128>>>(x, logd);
    apply_kernel<<<Bb * NCHUNK, 128>>>(x, logd);

    dim3 gg(Cc / BN, (Bb * Tt) / BM);  // (4, 256)
    gemm_kernel<<<gg, 256>>>(mixw, bias, out);
}

// round 4
// speedup vs baseline: 2.1912x; 2.1912x over previous
#include <cuda_runtime.h>
#include <cstdint>
#include <math.h>

// Problem dims
#define Bb 8
#define Tt 4096
#define Cc 512
#define NCHUNK 64
#define LCHUNK 64   // Tt / NCHUNK

// Scratch (device globals: no runtime allocation allowed)
__device__ __align__(256) float g_y[Bb * Tt * Cc];      // 64 MB intermediate y (tf32-rounded)
__device__ __align__(256) float g_A[Bb * NCHUNK * Cc];  // per-chunk weighted sums
__device__ __align__(256) float g_W[Cc * Cc];           // tf32-rounded weights

__device__ __forceinline__ float tf32_rn(float f) {
    uint32_t u;
    asm("cvt.rna.tf32.f32 %0, %1;" : "=r"(u) : "f"(f));
    return __uint_as_float(u);
}

// ---------------------------------------------------------------------------
// Kernel 1: per-chunk absolutely-weighted sums  A[b,k,c] = sum_j d^(t0+j) x
// ---------------------------------------------------------------------------
__global__ void __launch_bounds__(128) chunk_sum_kernel(
    const float* __restrict__ x, const float* __restrict__ logd)
{
    const int b = blockIdx.x / NCHUNK;
    const int k = blockIdx.x % NCHUNK;
    const int c = threadIdx.x * 4;

    float4 ld4 = *reinterpret_cast<const float4*>(logd + c);
    const float d0 = 1.0f / (1.0f + expf(-ld4.x));
    const float d1 = 1.0f / (1.0f + expf(-ld4.y));
    const float d2 = 1.0f / (1.0f + expf(-ld4.z));
    const float d3 = 1.0f / (1.0f + expf(-ld4.w));

    const float ft0 = (float)(k * LCHUNK);
    float w0 = exp2f(ft0 * log2f(d0));
    float w1 = exp2f(ft0 * log2f(d1));
    float w2 = exp2f(ft0 * log2f(d2));
    float w3 = exp2f(ft0 * log2f(d3));

    const float* xp = x + ((size_t)b * Tt + (size_t)k * LCHUNK) * Cc + c;

    float a0 = 0.f, a1 = 0.f, a2 = 0.f, a3 = 0.f;
#pragma unroll 8
    for (int j = 0; j < LCHUNK; ++j) {
        float4 v = *reinterpret_cast<const float4*>(xp + (size_t)j * Cc);
        a0 += w0 * v.x;
        a1 += w1 * v.y;
        a2 += w2 * v.z;
        a3 += w3 * v.w;
        w0 *= d0; w1 *= d1; w2 *= d2; w3 *= d3;
    }

    float4 r; r.x = a0; r.y = a1; r.z = a2; r.w = a3;
    *reinterpret_cast<float4*>(&g_A[((size_t)b * NCHUNK + k) * Cc + c]) = r;
}

// ---------------------------------------------------------------------------
// Kernel 2: prefix over chunks + local rescan; y = d^(T-1-t) * S, tf32-rounded
// ---------------------------------------------------------------------------
__global__ void __launch_bounds__(128) apply_kernel(
    const float* __restrict__ x, const float* __restrict__ logd)
{
    const int b = blockIdx.x / NCHUNK;
    const int k = blockIdx.x % NCHUNK;
    const int c = threadIdx.x * 4;

    float4 ld4 = *reinterpret_cast<const float4*>(logd + c);
    const float d0 = 1.0f / (1.0f + expf(-ld4.x));
    const float d1 = 1.0f / (1.0f + expf(-ld4.y));
    const float d2 = 1.0f / (1.0f + expf(-ld4.z));
    const float d3 = 1.0f / (1.0f + expf(-ld4.w));
    const float l20 = log2f(d0), l21 = log2f(d1), l22 = log2f(d2), l23 = log2f(d3);

    float P0 = 0.f, P1 = 0.f, P2 = 0.f, P3 = 0.f;
    const float* Aprow = g_A + (size_t)b * NCHUNK * Cc + c;
    for (int kk = 0; kk < k; ++kk) {
        float4 v = *reinterpret_cast<const float4*>(Aprow + (size_t)kk * Cc);
        P0 += v.x; P1 += v.y; P2 += v.z; P3 += v.w;
    }

    const int t0 = k * LCHUNK;
    const float ft0 = (float)t0;
    float w0 = exp2f(ft0 * l20);
    float w1 = exp2f(ft0 * l21);
    float w2 = exp2f(ft0 * l22);
    float w3 = exp2f(ft0 * l23);

    const float eb0 = (float)(Tt - 1 - t0) * l20;
    const float eb1 = (float)(Tt - 1 - t0) * l21;
    const float eb2 = (float)(Tt - 1 - t0) * l22;
    const float eb3 = (float)(Tt - 1 - t0) * l23;
    const float ee0 = (float)(Tt - 1 - t0 - (LCHUNK - 1)) * l20;
    const float ee1 = (float)(Tt - 1 - t0 - (LCHUNK - 1)) * l21;
    const float ee2 = (float)(Tt - 1 - t0 - (LCHUNK - 1)) * l22;
    const float ee3 = (float)(Tt - 1 - t0 - (LCHUNK - 1)) * l23;
    const bool ex0 = (eb0 < -100.f) && (ee0 > -140.f);
    const bool ex1 = (eb1 < -100.f) && (ee1 > -140.f);
    const bool ex2 = (eb2 < -100.f) && (ee2 > -140.f);
    const bool ex3 = (eb3 < -100.f) && (ee3 > -140.f);
    const bool anyex = ex0 | ex1 | ex2 | ex3;

    float pt0 = exp2f(eb0), pt1 = exp2f(eb1), pt2 = exp2f(eb2), pt3 = exp2f(eb3);
    const float i0 = 1.0f / d0, i1 = 1.0f / d1, i2 = 1.0f / d2, i3 = 1.0f / d3;

    float S0 = P0, S1 = P1, S2 = P2, S3 = P3;

    const float* xp = x + ((size_t)b * Tt + t0) * Cc + c;
    float* yp = g_y + ((size_t)b * Tt + t0) * Cc + c;

    if (!anyex) {
#pragma unroll 4
        for (int j = 0; j < LCHUNK; ++j) {
            float4 v = *reinterpret_cast<const float4*>(xp + (size_t)j * Cc);
            S0 += w0 * v.x; w0 *= d0;
            S1 += w1 * v.y; w1 *= d1;
            S2 += w2 * v.z; w2 *= d2;
            S3 += w3 * v.w; w3 *= d3;
            float4 r;
            r.x = tf32_rn(pt0 * S0); r.y = tf32_rn(pt1 * S1);
            r.z = tf32_rn(pt2 * S2); r.w = tf32_rn(pt3 * S3);
            pt0 *= i0; pt1 *= i1; pt2 *= i2; pt3 *= i3;
            *reinterpret_cast<float4*>(yp + (size_t)j * Cc) = r;
        }
    } else {
        for (int j = 0; j < LCHUNK; ++j) {
            const float tj = (float)(Tt - 1 - t0 - j);
            pt0 = ex0 ? exp2f(tj * l20) : pt0;
            pt1 = ex1 ? exp2f(tj * l21) : pt1;
            pt2 = ex2 ? exp2f(tj * l22) : pt2;
            pt3 = ex3 ? exp2f(tj * l23) : pt3;
            float4 v = *reinterpret_cast<const float4*>(xp + (size_t)j * Cc);
            S0 += w0 * v.x; w0 *= d0;
            S1 += w1 * v.y; w1 *= d1;
            S2 += w2 * v.z; w2 *= d2;
            S3 += w3 * v.w; w3 *= d3;
            float4 r;
            r.x = tf32_rn(pt0 * S0); r.y = tf32_rn(pt1 * S1);
            r.z = tf32_rn(pt2 * S2); r.w = tf32_rn(pt3 * S3);
            pt0 = ex0 ? pt0 : pt0 * i0;
            pt1 = ex1 ? pt1 : pt1 * i1;
            pt2 = ex2 ? pt2 : pt2 * i2;
            pt3 = ex3 ? pt3 : pt3 * i3;
            *reinterpret_cast<float4*>(yp + (size_t)j * Cc) = r;
        }
    }
}

// ---------------------------------------------------------------------------
// Kernel 2b: round W to tf32 once
// ---------------------------------------------------------------------------
__global__ void __launch_bounds__(256) wconv_kernel(const float* __restrict__ W)
{
    int i = (blockIdx.x * 256 + threadIdx.x) * 4;
    float4 v = *reinterpret_cast<const float4*>(W + i);
    v.x = tf32_rn(v.x); v.y = tf32_rn(v.y); v.z = tf32_rn(v.z); v.w = tf32_rn(v.w);
    *reinterpret_cast<float4*>(&g_W[i]) = v;
}

// ---------------------------------------------------------------------------
// Kernel 3: tf32 tensor-core GEMM via mma.sync (sm_80+ path, works on sm_100).
// out[32768,512] = y @ W^T + bias.
// CTA tile 128x256x32, 256 threads (8 warps, 2m x 4n, warp tile 64x64),
// 3-stage cp.async pipeline, smem pitch 36 floats (conflict-free frag loads).
// ---------------------------------------------------------------------------
#define BM 128
#define BN 256
#define KC 32
#define NCHK (Cc / KC)           // 16
#define PITCH 36                 // floats per smem row
#define A_ST_FLOATS (BM * PITCH) // 4608
#define B_ST_FLOATS (BN * PITCH) // 9216
#define STAGE_FLOATS (A_ST_FLOATS + B_ST_FLOATS)  // 13824
#define NSTAGE 3
#define SMEM_TOTAL (NSTAGE * STAGE_FLOATS * 4)    // 165888 B

__device__ __forceinline__ void mma_tf32(float* d, const uint32_t* a, const uint32_t* b) {
    asm volatile(
        "mma.sync.aligned.m16n8k8.row.col.f32.tf32.tf32.f32 "
        "{%0,%1,%2,%3}, {%4,%5,%6,%7}, {%8,%9}, {%0,%1,%2,%3};"
        : "+f"(d[0]), "+f"(d[1]), "+f"(d[2]), "+f"(d[3])
        : "r"(a[0]), "r"(a[1]), "r"(a[2]), "r"(a[3]), "r"(b[0]), "r"(b[1]));
}

__global__ void __launch_bounds__(256, 1) gemm_mma_kernel(
    const float* __restrict__ bias, float* __restrict__ out)
{
    extern __shared__ __align__(128) float smem[];

    const int tid = threadIdx.x;
    const int wid = tid >> 5;
    const int lane = tid & 31;
    const int q = lane >> 2;   // 0..7
    const int cq = lane & 3;   // 0..3

    const int bm = blockIdx.x >> 1;   // 0..255
    const int bn = blockIdx.x & 1;    // 0..1
    const int wm = wid >> 2;          // 0..1
    const int wn = wid & 3;           // 0..3

    const float* Abase = g_y + (size_t)(bm * BM) * Cc;
    const float* Bbase = g_W + (size_t)(bn * BN) * Cc;

    // cp.async issue helper: 3072 16B-segments per chunk (A:1024, B:2048)
    auto issue_chunk = [&](int ch) {
        float* stg = smem + (ch % NSTAGE) * STAGE_FLOATS;
        const int kof = ch * KC;
#pragma unroll
        for (int i = 0; i < 12; ++i) {
            const int u = tid + i * 256;
            const float* src;
            float* dst;
            if (u < 1024) {
                const int row = u >> 3, seg = u & 7;
                src = Abase + (size_t)row * Cc + kof + seg * 4;
                dst = stg + row * PITCH + seg * 4;
            } else {
                const int v = u - 1024;
                const int row = v >> 3, seg = v & 7;
                src = Bbase + (size_t)row * Cc + kof + seg * 4;
                dst = stg + A_ST_FLOATS + row * PITCH + seg * 4;
            }
            uint32_t daddr = (uint32_t)__cvta_generic_to_shared(dst);
            asm volatile("cp.async.cg.shared.global [%0], [%1], 16;"
                         :: "r"(daddr), "l"(src) : "memory");
        }
        asm volatile("cp.async.commit_group;" ::: "memory");
    };

    // Prologue: chunks 0,1
    issue_chunk(0);
    issue_chunk(1);

    float acc[4][8][4];
#pragma unroll
    for (int mt = 0; mt < 4; ++mt)
#pragma unroll
        for (int nt = 0; nt < 8; ++nt)
#pragma unroll
            for (int e = 0; e < 4; ++e) acc[mt][nt][e] = 0.f;

#pragma unroll 1
    for (int ch = 0; ch < NCHK; ++ch) {
        __syncthreads();   // previous chunk's compute done; safe to overwrite buf
        if (ch + 2 < NCHK) issue_chunk(ch + 2);
        if (ch < 14) {
            asm volatile("cp.async.wait_group 2;" ::: "memory");
        } else if (ch == 14) {
            asm volatile("cp.async.wait_group 1;" ::: "memory");
        } else {
            asm volatile("cp.async.wait_group 0;" ::: "memory");
        }
        __syncthreads();

        const float* As = smem + (ch % NSTAGE) * STAGE_FLOATS;
        const float* Bs = As + A_ST_FLOATS;
        const uint32_t* Au = reinterpret_cast<const uint32_t*>(As);
        const uint32_t* Bu = reinterpret_cast<const uint32_t*>(Bs);

#pragma unroll
        for (int ks = 0; ks < 4; ++ks) {
            const int kk8 = ks * 8;
            uint32_t a[4][4], b[8][2];
#pragma unroll
            for (int mt = 0; mt < 4; ++mt) {
                const int m0 = wm * 64 + mt * 16;
                a[mt][0] = Au[(m0 + q) * PITCH + kk8 + cq];
                a[mt][1] = Au[(m0 + q + 8) * PITCH + kk8 + cq];
                a[mt][2] = Au[(m0 + q) * PITCH + kk8 + cq + 4];
                a[mt][3] = Au[(m0 + q + 8) * PITCH + kk8 + cq + 4];
            }
#pragma unroll
            for (int nt = 0; nt < 8; ++nt) {
                const int n0 = wn * 64 + nt * 8;
                b[nt][0] = Bu[(n0 + q) * PITCH + kk8 + cq];
                b[nt][1] = Bu[(n0 + q) * PITCH + kk8 + cq + 4];
            }
#pragma unroll
            for (int mt = 0; mt < 4; ++mt)
#pragma unroll
                for (int nt = 0; nt < 8; ++nt)
                    mma_tf32(acc[mt][nt], a[mt], b[nt]);
        }
    }

    // Epilogue: bias + store (float2 per row-half per ntile)
#pragma unroll
    for (int nt = 0; nt < 8; ++nt) {
        const int col = bn * BN + wn * 64 + nt * 8 + cq * 2;
        const float b0 = __ldg(bias + col);
        const float b1 = __ldg(bias + col + 1);
#pragma unroll
        for (int mt = 0; mt < 4; ++mt) {
            const size_t row0 = (size_t)(bm * BM + wm * 64 + mt * 16 + q);
            float2 v0, v1;
            v0.x = acc[mt][nt][0] + b0; v0.y = acc[mt][nt][1] + b1;
            v1.x = acc[mt][nt][2] + b0; v1.y = acc[mt][nt][3] + b1;
            *reinterpret_cast<float2*>(out + row0 * Cc + col) = v0;
            *reinterpret_cast<float2*>(out + (row0 + 8) * Cc + col) = v1;
        }
    }
}

// ---------------------------------------------------------------------------
extern "C" void kernel_launch(void* const* d_in, const int* in_sizes, int n_in,
                              void* d_out, int out_size)
{
    (void)in_sizes; (void)n_in; (void)out_size;
    const float* x    = (const float*)d_in[0];
    const float* logd = (const float*)d_in[1];
    const float* mixw = (const float*)d_in[2];
    const float* bias = (const float*)d_in[3];
    float* out = (float*)d_out;

    cudaFuncSetAttribute(gemm_mma_kernel, cudaFuncAttributeMaxDynamicSharedMemorySize,
                         SMEM_TOTAL);

    chunk_sum_kernel<<<Bb * NCHUNK, 128>>>(x, logd);
    apply_kernel<<<Bb * NCHUNK, 128>>>(x, logd);
    wconv_kernel<<<Cc * Cc / 1024, 256>>>(mixw);
    gemm_mma_kernel<<<512, 256, SMEM_TOTAL>>>(bias, out);
}

// round 6
// speedup vs baseline: 2.1936x; 1.0011x over previous
#include <cuda_runtime.h>
#include <cstdint>
#include <math.h>

// Problem dims
#define Bb 8
#define Tt 4096
#define Cc 512
#define NCHUNK 64
#define LCHUNK 64   // Tt / NCHUNK

// Scratch (device globals: no runtime allocation allowed)
__device__ __align__(256) float g_y[Bb * Tt * Cc];      // 64 MB intermediate y (tf32-rounded)
__device__ __align__(256) float g_A[Bb * NCHUNK * Cc];  // per-chunk weighted sums
__device__ __align__(256) float g_W[Cc * Cc];           // tf32-rounded weights

__device__ __forceinline__ float tf32_rn(float f) {
    uint32_t u;
    asm("cvt.rna.tf32.f32 %0, %1;" : "=r"(u) : "f"(f));
    return __uint_as_float(u);
}

// ---------------------------------------------------------------------------
// Kernel 1: per-chunk absolutely-weighted sums  A[b,k,c] = sum_j d^(t0+j) x
// Also converts one float4 of W to tf32 per thread (fused wconv).
// ---------------------------------------------------------------------------
__global__ void __launch_bounds__(128) chunk_sum_kernel(
    const float* __restrict__ x, const float* __restrict__ logd,
    const float* __restrict__ W)
{
    const int b = blockIdx.x / NCHUNK;
    const int k = blockIdx.x % NCHUNK;
    const int c = threadIdx.x * 4;

    // fused W tf32 conversion: 512 blocks * 128 threads * 4 = 262144 = Cc*Cc
    {
        const int i = (blockIdx.x * 128 + threadIdx.x) * 4;
        float4 v = *reinterpret_cast<const float4*>(W + i);
        v.x = tf32_rn(v.x); v.y = tf32_rn(v.y); v.z = tf32_rn(v.z); v.w = tf32_rn(v.w);
        *reinterpret_cast<float4*>(&g_W[i]) = v;
    }

    float4 ld4 = *reinterpret_cast<const float4*>(logd + c);
    const float d0 = 1.0f / (1.0f + expf(-ld4.x));
    const float d1 = 1.0f / (1.0f + expf(-ld4.y));
    const float d2 = 1.0f / (1.0f + expf(-ld4.z));
    const float d3 = 1.0f / (1.0f + expf(-ld4.w));

    const float ft0 = (float)(k * LCHUNK);
    float w0 = exp2f(ft0 * log2f(d0));
    float w1 = exp2f(ft0 * log2f(d1));
    float w2 = exp2f(ft0 * log2f(d2));
    float w3 = exp2f(ft0 * log2f(d3));

    const float* xp = x + ((size_t)b * Tt + (size_t)k * LCHUNK) * Cc + c;

    float a0 = 0.f, a1 = 0.f, a2 = 0.f, a3 = 0.f;
#pragma unroll 8
    for (int j = 0; j < LCHUNK; ++j) {
        float4 v = *reinterpret_cast<const float4*>(xp + (size_t)j * Cc);
        a0 += w0 * v.x;
        a1 += w1 * v.y;
        a2 += w2 * v.z;
        a3 += w3 * v.w;
        w0 *= d0; w1 *= d1; w2 *= d2; w3 *= d3;
    }

    float4 r; r.x = a0; r.y = a1; r.z = a2; r.w = a3;
    *reinterpret_cast<float4*>(&g_A[((size_t)b * NCHUNK + k) * Cc + c]) = r;
}

// ---------------------------------------------------------------------------
// Kernel 2: prefix over chunks + local rescan; y = d^(T-1-t) * S, tf32-rounded
// ---------------------------------------------------------------------------
__global__ void __launch_bounds__(128) apply_kernel(
    const float* __restrict__ x, const float* __restrict__ logd)
{
    const int b = blockIdx.x / NCHUNK;
    const int k = blockIdx.x % NCHUNK;
    const int c = threadIdx.x * 4;

    float4 ld4 = *reinterpret_cast<const float4*>(logd + c);
    const float d0 = 1.0f / (1.0f + expf(-ld4.x));
    const float d1 = 1.0f / (1.0f + expf(-ld4.y));
    const float d2 = 1.0f / (1.0f + expf(-ld4.z));
    const float d3 = 1.0f / (1.0f + expf(-ld4.w));
    const float l20 = log2f(d0), l21 = log2f(d1), l22 = log2f(d2), l23 = log2f(d3);

    float P0 = 0.f, P1 = 0.f, P2 = 0.f, P3 = 0.f;
    const float* Aprow = g_A + (size_t)b * NCHUNK * Cc + c;
    for (int kk = 0; kk < k; ++kk) {
        float4 v = *reinterpret_cast<const float4*>(Aprow + (size_t)kk * Cc);
        P0 += v.x; P1 += v.y; P2 += v.z; P3 += v.w;
    }

    const int t0 = k * LCHUNK;
    const float ft0 = (float)t0;
    float w0 = exp2f(ft0 * l20);
    float w1 = exp2f(ft0 * l21);
    float w2 = exp2f(ft0 * l22);
    float w3 = exp2f(ft0 * l23);

    const float eb0 = (float)(Tt - 1 - t0) * l20;
    const float eb1 = (float)(Tt - 1 - t0) * l21;
    const float eb2 = (float)(Tt - 1 - t0) * l22;
    const float eb3 = (float)(Tt - 1 - t0) * l23;
    const float ee0 = (float)(Tt - 1 - t0 - (LCHUNK - 1)) * l20;
    const float ee1 = (float)(Tt - 1 - t0 - (LCHUNK - 1)) * l21;
    const float ee2 = (float)(Tt - 1 - t0 - (LCHUNK - 1)) * l22;
    const float ee3 = (float)(Tt - 1 - t0 - (LCHUNK - 1)) * l23;
    const bool ex0 = (eb0 < -100.f) && (ee0 > -140.f);
    const bool ex1 = (eb1 < -100.f) && (ee1 > -140.f);
    const bool ex2 = (eb2 < -100.f) && (ee2 > -140.f);
    const bool ex3 = (eb3 < -100.f) && (ee3 > -140.f);
    const bool anyex = ex0 | ex1 | ex2 | ex3;

    float pt0 = exp2f(eb0), pt1 = exp2f(eb1), pt2 = exp2f(eb2), pt3 = exp2f(eb3);
    const float i0 = 1.0f / d0, i1 = 1.0f / d1, i2 = 1.0f / d2, i3 = 1.0f / d3;

    float S0 = P0, S1 = P1, S2 = P2, S3 = P3;

    const float* xp = x + ((size_t)b * Tt + t0) * Cc + c;
    float* yp = g_y + ((size_t)b * Tt + t0) * Cc + c;

    if (!anyex) {
#pragma unroll 4
        for (int j = 0; j < LCHUNK; ++j) {
            float4 v = *reinterpret_cast<const float4*>(xp + (size_t)j * Cc);
            S0 += w0 * v.x; w0 *= d0;
            S1 += w1 * v.y; w1 *= d1;
            S2 += w2 * v.z; w2 *= d2;
            S3 += w3 * v.w; w3 *= d3;
            float4 r;
            r.x = tf32_rn(pt0 * S0); r.y = tf32_rn(pt1 * S1);
            r.z = tf32_rn(pt2 * S2); r.w = tf32_rn(pt3 * S3);
            pt0 *= i0; pt1 *= i1; pt2 *= i2; pt3 *= i3;
            *reinterpret_cast<float4*>(yp + (size_t)j * Cc) = r;
        }
    } else {
        for (int j = 0; j < LCHUNK; ++j) {
            const float tj = (float)(Tt - 1 - t0 - j);
            pt0 = ex0 ? exp2f(tj * l20) : pt0;
            pt1 = ex1 ? exp2f(tj * l21) : pt1;
            pt2 = ex2 ? exp2f(tj * l22) : pt2;
            pt3 = ex3 ? exp2f(tj * l23) : pt3;
            float4 v = *reinterpret_cast<const float4*>(xp + (size_t)j * Cc);
            S0 += w0 * v.x; w0 *= d0;
            S1 += w1 * v.y; w1 *= d1;
            S2 += w2 * v.z; w2 *= d2;
            S3 += w3 * v.w; w3 *= d3;
            float4 r;
            r.x = tf32_rn(pt0 * S0); r.y = tf32_rn(pt1 * S1);
            r.z = tf32_rn(pt2 * S2); r.w = tf32_rn(pt3 * S3);
            pt0 = ex0 ? pt0 : pt0 * i0;
            pt1 = ex1 ? pt1 : pt1 * i1;
            pt2 = ex2 ? pt2 : pt2 * i2;
            pt3 = ex3 ? pt3 : pt3 * i3;
            *reinterpret_cast<float4*>(yp + (size_t)j * Cc) = r;
        }
    }
}

// ---------------------------------------------------------------------------
// Kernel 3: tf32 tensor-core GEMM via mma.sync. out = y @ W^T + bias.
// CTA tile 128x256x32, 256 threads (8 warps 2m x 4n, warp tile 64x64),
// 3-stage cp.async pipeline (1 sync/chunk), register double-buffered frags,
// smem pitch 36 floats (conflict-free scalar LDS).
// ---------------------------------------------------------------------------
#define BM 128
#define BN 256
#define KC 32
#define NCHK (Cc / KC)           // 16
#define PITCH 36                 // floats per smem row
#define A_ST_FLOATS (BM * PITCH) // 4608
#define B_ST_FLOATS (BN * PITCH) // 9216
#define STAGE_FLOATS (A_ST_FLOATS + B_ST_FLOATS)  // 13824
#define NSTAGE 3
#define SMEM_TOTAL (NSTAGE * STAGE_FLOATS * 4)    // 165888 B

__device__ __forceinline__ void mma_tf32(float* d, const uint32_t* a, const uint32_t* b) {
    asm volatile(
        "mma.sync.aligned.m16n8k8.row.col.f32.tf32.tf32.f32 "
        "{%0,%1,%2,%3}, {%4,%5,%6,%7}, {%8,%9}, {%0,%1,%2,%3};"
        : "+f"(d[0]), "+f"(d[1]), "+f"(d[2]), "+f"(d[3])
        : "r"(a[0]), "r"(a[1]), "r"(a[2]), "r"(a[3]), "r"(b[0]), "r"(b[1]));
}

__global__ void __launch_bounds__(256, 1) gemm_mma_kernel(
    const float* __restrict__ bias, float* __restrict__ out)
{
    extern __shared__ __align__(128) float smem[];

    const int tid = threadIdx.x;
    const int wid = tid >> 5;
    const int lane = tid & 31;
    const int q = lane >> 2;   // 0..7
    const int cq = lane & 3;   // 0..3

    const int bm = blockIdx.x >> 1;   // 0..255
    const int bn = blockIdx.x & 1;    // 0..1
    const int wm = wid >> 2;          // 0..1
    const int wn = wid & 3;           // 0..3

    const float* Abase = g_y + (size_t)(bm * BM) * Cc;
    const float* Bbase = g_W + (size_t)(bn * BN) * Cc;

    // cp.async issue helper: 3072 16B-segments per chunk (A:1024, B:2048)
    auto issue_chunk = [&](int ch) {
        float* stg = smem + (ch % NSTAGE) * STAGE_FLOATS;
        const int kof = ch * KC;
#pragma unroll
        for (int i = 0; i < 12; ++i) {
            const int u = tid + i * 256;
            const float* src;
            float* dst;
            if (u < 1024) {
                const int row = u >> 3, seg = u & 7;
                src = Abase + (size_t)row * Cc + kof + seg * 4;
                dst = stg + row * PITCH + seg * 4;
            } else {
                const int v = u - 1024;
                const int row = v >> 3, seg = v & 7;
                src = Bbase + (size_t)row * Cc + kof + seg * 4;
                dst = stg + A_ST_FLOATS + row * PITCH + seg * 4;
            }
            uint32_t daddr = (uint32_t)__cvta_generic_to_shared(dst);
            asm volatile("cp.async.cg.shared.global [%0], [%1], 16;"
                         :: "r"(daddr), "l"(src) : "memory");
        }
        asm volatile("cp.async.commit_group;" ::: "memory");
    };

    // Prologue: chunks 0,1
    issue_chunk(0);
    issue_chunk(1);

    float acc[4][8][4];
#pragma unroll
    for (int mt = 0; mt < 4; ++mt)
#pragma unroll
        for (int nt = 0; nt < 8; ++nt)
#pragma unroll
            for (int e = 0; e < 4; ++e) acc[mt][nt][e] = 0.f;

    uint32_t aR[2][4][4], bR[2][8][2];

#pragma unroll 1
    for (int ch = 0; ch < NCHK; ++ch) {
        if (ch < NCHK - 1) {
            asm volatile("cp.async.wait_group 1;" ::: "memory");
        } else {
            asm volatile("cp.async.wait_group 0;" ::: "memory");
        }
        __syncthreads();   // chunk ch visible to all; compute(ch-1) done by all

        if (ch + 2 < NCHK) issue_chunk(ch + 2);

        const float* As = smem + (ch % NSTAGE) * STAGE_FLOATS;
        const uint32_t* Au = reinterpret_cast<const uint32_t*>(As);
        const uint32_t* Bu = reinterpret_cast<const uint32_t*>(As + A_ST_FLOATS);

        auto lfrag = [&](int ks, uint32_t (*a)[4], uint32_t (*b)[2]) {
            const int kk8 = ks * 8;
#pragma unroll
            for (int mt = 0; mt < 4; ++mt) {
                const int m0 = wm * 64 + mt * 16;
                a[mt][0] = Au[(m0 + q) * PITCH + kk8 + cq];
                a[mt][1] = Au[(m0 + q + 8) * PITCH + kk8 + cq];
                a[mt][2] = Au[(m0 + q) * PITCH + kk8 + cq + 4];
                a[mt][3] = Au[(m0 + q + 8) * PITCH + kk8 + cq + 4];
            }
#pragma unroll
            for (int nt = 0; nt < 8; ++nt) {
                const int n0 = wn * 64 + nt * 8;
                b[nt][0] = Bu[(n0 + q) * PITCH + kk8 + cq];
                b[nt][1] = Bu[(n0 + q) * PITCH + kk8 + cq + 4];
            }
        };

        lfrag(0, aR[0], bR[0]);
#pragma unroll
        for (int ks = 0; ks < 4; ++ks) {
            if (ks < 3) lfrag(ks + 1, aR[(ks + 1) & 1], bR[(ks + 1) & 1]);
#pragma unroll
            for (int mt = 0; mt < 4; ++mt)
#pragma unroll
                for (int nt = 0; nt < 8; ++nt)
                    mma_tf32(acc[mt][nt], aR[ks & 1][mt], bR[ks & 1][nt]);
        }
    }

    // Epilogue: bias + store
#pragma unroll
    for (int nt = 0; nt < 8; ++nt) {
        const int col = bn * BN + wn * 64 + nt * 8 + cq * 2;
        const float b0 = __ldg(bias + col);
        const float b1 = __ldg(bias + col + 1);
#pragma unroll
        for (int mt = 0; mt < 4; ++mt) {
            const size_t row0 = (size_t)(bm * BM + wm * 64 + mt * 16 + q);
            float2 v0, v1;
            v0.x = acc[mt][nt][0] + b0; v0.y = acc[mt][nt][1] + b1;
            v1.x = acc[mt][nt][2] + b0; v1.y = acc[mt][nt][3] + b1;
            *reinterpret_cast<float2*>(out + row0 * Cc + col) = v0;
            *reinterpret_cast<float2*>(out + (row0 + 8) * Cc + col) = v1;
        }
    }
}

// ---------------------------------------------------------------------------
extern "C" void kernel_launch(void* const* d_in, const int* in_sizes, int n_in,
                              void* d_out, int out_size)
{
    (void)in_sizes; (void)n_in; (void)out_size;
    const float* x    = (const float*)d_in[0];
    const float* logd = (const float*)d_in[1];
    const float* mixw = (const float*)d_in[2];
    const float* bias = (const float*)d_in[3];
    float* out = (float*)d_out;

    cudaFuncSetAttribute(gemm_mma_kernel, cudaFuncAttributeMaxDynamicSharedMemorySize,
                         SMEM_TOTAL);

    chunk_sum_kernel<<<Bb * NCHUNK, 128>>>(x, logd, mixw);
    apply_kernel<<<Bb * NCHUNK, 128>>>(x, logd);
    gemm_mma_kernel<<<512, 256, SMEM_TOTAL>>>(bias, out);
}

// round 7
// speedup vs baseline: 2.2051x; 1.0052x over previous
#include <cuda_runtime.h>
#include <cstdint>
#include <math.h>

// Problem dims
#define Bb 8
#define Tt 4096
#define Cc 512
#define NCHUNK 64
#define LCHUNK 64   // Tt / NCHUNK

// Scratch (device globals: no runtime allocation allowed)
__device__ __align__(256) float g_y[Bb * Tt * Cc];      // 64 MB intermediate y (tf32-rounded)
__device__ __align__(256) float g_A[Bb * NCHUNK * Cc];  // per-chunk weighted sums
__device__ __align__(256) float g_W[Cc * Cc];           // tf32-rounded weights

__device__ __forceinline__ float tf32_rn(float f) {
    uint32_t u;
    asm("cvt.rna.tf32.f32 %0, %1;" : "=r"(u) : "f"(f));
    return __uint_as_float(u);
}

// ---------------------------------------------------------------------------
// Kernel 1: per-chunk absolutely-weighted sums  A[b,k,c] = sum_j d^(t0+j) x
// Also converts one float4 of W to tf32 per thread (fused wconv).
// ---------------------------------------------------------------------------
__global__ void __launch_bounds__(128) chunk_sum_kernel(
    const float* __restrict__ x, const float* __restrict__ logd,
    const float* __restrict__ W)
{
    const int b = blockIdx.x / NCHUNK;
    const int k = blockIdx.x % NCHUNK;
    const int c = threadIdx.x * 4;

    // fused W tf32 conversion: 512 blocks * 128 threads * 4 = 262144 = Cc*Cc
    {
        const int i = (blockIdx.x * 128 + threadIdx.x) * 4;
        float4 v = *reinterpret_cast<const float4*>(W + i);
        v.x = tf32_rn(v.x); v.y = tf32_rn(v.y); v.z = tf32_rn(v.z); v.w = tf32_rn(v.w);
        *reinterpret_cast<float4*>(&g_W[i]) = v;
    }

    float4 ld4 = *reinterpret_cast<const float4*>(logd + c);
    const float d0 = 1.0f / (1.0f + expf(-ld4.x));
    const float d1 = 1.0f / (1.0f + expf(-ld4.y));
    const float d2 = 1.0f / (1.0f + expf(-ld4.z));
    const float d3 = 1.0f / (1.0f + expf(-ld4.w));

    const float ft0 = (float)(k * LCHUNK);
    float w0 = exp2f(ft0 * log2f(d0));
    float w1 = exp2f(ft0 * log2f(d1));
    float w2 = exp2f(ft0 * log2f(d2));
    float w3 = exp2f(ft0 * log2f(d3));

    const float* xp = x + ((size_t)b * Tt + (size_t)k * LCHUNK) * Cc + c;

    float a0 = 0.f, a1 = 0.f, a2 = 0.f, a3 = 0.f;
#pragma unroll 8
    for (int j = 0; j < LCHUNK; ++j) {
        float4 v = *reinterpret_cast<const float4*>(xp + (size_t)j * Cc);
        a0 += w0 * v.x;
        a1 += w1 * v.y;
        a2 += w2 * v.z;
        a3 += w3 * v.w;
        w0 *= d0; w1 *= d1; w2 *= d2; w3 *= d3;
    }

    float4 r; r.x = a0; r.y = a1; r.z = a2; r.w = a3;
    *reinterpret_cast<float4*>(&g_A[((size_t)b * NCHUNK + k) * Cc + c]) = r;
}

// ---------------------------------------------------------------------------
// Kernel 2: prefix over chunks + local rescan; y = d^(T-1-t) * S, tf32-rounded
// ---------------------------------------------------------------------------
__global__ void __launch_bounds__(128) apply_kernel(
    const float* __restrict__ x, const float* __restrict__ logd)
{
    const int b = blockIdx.x / NCHUNK;
    const int k = blockIdx.x % NCHUNK;
    const int c = threadIdx.x * 4;

    float4 ld4 = *reinterpret_cast<const float4*>(logd + c);
    const float d0 = 1.0f / (1.0f + expf(-ld4.x));
    const float d1 = 1.0f / (1.0f + expf(-ld4.y));
    const float d2 = 1.0f / (1.0f + expf(-ld4.z));
    const float d3 = 1.0f / (1.0f + expf(-ld4.w));
    const float l20 = log2f(d0), l21 = log2f(d1), l22 = log2f(d2), l23 = log2f(d3);

    float P0 = 0.f, P1 = 0.f, P2 = 0.f, P3 = 0.f;
    const float* Aprow = g_A + (size_t)b * NCHUNK * Cc + c;
    for (int kk = 0; kk < k; ++kk) {
        float4 v = *reinterpret_cast<const float4*>(Aprow + (size_t)kk * Cc);
        P0 += v.x; P1 += v.y; P2 += v.z; P3 += v.w;
    }

    const int t0 = k * LCHUNK;
    const float ft0 = (float)t0;
    float w0 = exp2f(ft0 * l20);
    float w1 = exp2f(ft0 * l21);
    float w2 = exp2f(ft0 * l22);
    float w3 = exp2f(ft0 * l23);

    const float eb0 = (float)(Tt - 1 - t0) * l20;
    const float eb1 = (float)(Tt - 1 - t0) * l21;
    const float eb2 = (float)(Tt - 1 - t0) * l22;
    const float eb3 = (float)(Tt - 1 - t0) * l23;
    const float ee0 = (float)(Tt - 1 - t0 - (LCHUNK - 1)) * l20;
    const float ee1 = (float)(Tt - 1 - t0 - (LCHUNK - 1)) * l21;
    const float ee2 = (float)(Tt - 1 - t0 - (LCHUNK - 1)) * l22;
    const float ee3 = (float)(Tt - 1 - t0 - (LCHUNK - 1)) * l23;
    const bool ex0 = (eb0 < -100.f) && (ee0 > -140.f);
    const bool ex1 = (eb1 < -100.f) && (ee1 > -140.f);
    const bool ex2 = (eb2 < -100.f) && (ee2 > -140.f);
    const bool ex3 = (eb3 < -100.f) && (ee3 > -140.f);
    const bool anyex = ex0 | ex1 | ex2 | ex3;

    float pt0 = exp2f(eb0), pt1 = exp2f(eb1), pt2 = exp2f(eb2), pt3 = exp2f(eb3);
    const float i0 = 1.0f / d0, i1 = 1.0f / d1, i2 = 1.0f / d2, i3 = 1.0f / d3;

    float S0 = P0, S1 = P1, S2 = P2, S3 = P3;

    const float* xp = x + ((size_t)b * Tt + t0) * Cc + c;
    float* yp = g_y + ((size_t)b * Tt + t0) * Cc + c;

    if (!anyex) {
#pragma unroll 4
        for (int j = 0; j < LCHUNK; ++j) {
            float4 v = *reinterpret_cast<const float4*>(xp + (size_t)j * Cc);
            S0 += w0 * v.x; w0 *= d0;
            S1 += w1 * v.y; w1 *= d1;
            S2 += w2 * v.z; w2 *= d2;
            S3 += w3 * v.w; w3 *= d3;
            float4 r;
            r.x = tf32_rn(pt0 * S0); r.y = tf32_rn(pt1 * S1);
            r.z = tf32_rn(pt2 * S2); r.w = tf32_rn(pt3 * S3);
            pt0 *= i0; pt1 *= i1; pt2 *= i2; pt3 *= i3;
            *reinterpret_cast<float4*>(yp + (size_t)j * Cc) = r;
        }
    } else {
        for (int j = 0; j < LCHUNK; ++j) {
            const float tj = (float)(Tt - 1 - t0 - j);
            pt0 = ex0 ? exp2f(tj * l20) : pt0;
            pt1 = ex1 ? exp2f(tj * l21) : pt1;
            pt2 = ex2 ? exp2f(tj * l22) : pt2;
            pt3 = ex3 ? exp2f(tj * l23) : pt3;
            float4 v = *reinterpret_cast<const float4*>(xp + (size_t)j * Cc);
            S0 += w0 * v.x; w0 *= d0;
            S1 += w1 * v.y; w1 *= d1;
            S2 += w2 * v.z; w2 *= d2;
            S3 += w3 * v.w; w3 *= d3;
            float4 r;
            r.x = tf32_rn(pt0 * S0); r.y = tf32_rn(pt1 * S1);
            r.z = tf32_rn(pt2 * S2); r.w = tf32_rn(pt3 * S3);
            pt0 = ex0 ? pt0 : pt0 * i0;
            pt1 = ex1 ? pt1 : pt1 * i1;
            pt2 = ex2 ? pt2 : pt2 * i2;
            pt3 = ex3 ? pt3 : pt3 * i3;
            *reinterpret_cast<float4*>(yp + (size_t)j * Cc) = r;
        }
    }
}

// ---------------------------------------------------------------------------
// Kernel 3: tf32 tensor-core GEMM via mma.sync + ldmatrix fragment loads.
// out = y @ W^T + bias. CTA tile 128x256x32, 256 threads (8 warps 2m x 4n,
// warp tile 64x64), 3-stage cp.async pipeline, LDSM.x4 on 32-bit data
// (8x4-word blocks match the tf32 fragment map), pitch 36 floats.
// ---------------------------------------------------------------------------
#define BM 128
#define BN 256
#define KC 32
#define NCHK (Cc / KC)           // 16
#define PITCH 36                 // floats per smem row
#define A_ST_FLOATS (BM * PITCH) // 4608
#define B_ST_FLOATS (BN * PITCH) // 9216
#define STAGE_FLOATS (A_ST_FLOATS + B_ST_FLOATS)  // 13824
#define NSTAGE 3
#define SMEM_TOTAL (NSTAGE * STAGE_FLOATS * 4)    // 165888 B

__device__ __forceinline__ void mma_tf32(float* d, const uint32_t* a, const uint32_t* b) {
    asm volatile(
        "mma.sync.aligned.m16n8k8.row.col.f32.tf32.tf32.f32 "
        "{%0,%1,%2,%3}, {%4,%5,%6,%7}, {%8,%9}, {%0,%1,%2,%3};"
        : "+f"(d[0]), "+f"(d[1]), "+f"(d[2]), "+f"(d[3])
        : "r"(a[0]), "r"(a[1]), "r"(a[2]), "r"(a[3]), "r"(b[0]), "r"(b[1]));
}

__device__ __forceinline__ void ldsm_x4(uint32_t* r, uint32_t saddr) {
    asm volatile(
        "ldmatrix.sync.aligned.m8n8.x4.shared.b16 {%0,%1,%2,%3}, [%4];"
        : "=r"(r[0]), "=r"(r[1]), "=r"(r[2]), "=r"(r[3]) : "r"(saddr));
}

__global__ void __launch_bounds__(256, 1) gemm_mma_kernel(
    const float* __restrict__ bias, float* __restrict__ out)
{
    extern __shared__ __align__(128) float smem[];

    const int tid = threadIdx.x;
    const int wid = tid >> 5;
    const int lane = tid & 31;
    const int q = lane >> 2;   // 0..7
    const int cq = lane & 3;   // 0..3

    const int bm = blockIdx.x >> 1;   // 0..255
    const int bn = blockIdx.x & 1;    // 0..1
    const int wm = wid >> 2;          // 0..1
    const int wn = wid & 3;           // 0..3

    const float* Abase = g_y + (size_t)(bm * BM) * Cc;
    const float* Bbase = g_W + (size_t)(bn * BN) * Cc;

    const uint32_t smemS = (uint32_t)__cvta_generic_to_shared(smem);

    // ldmatrix per-lane row addresses (in words, relative to tile start):
    // A: blocks {a0,a1,a2,a3} = {(m0,k8),(m0+8,k8),(m0,k8+4),(m0+8,k8+4)}
    const int rowA = (lane & 7) + ((lane >> 3) & 1) * 8;
    const int colA = (lane >> 4) * 4;
    // B pair p: blocks {b[2p][0],b[2p][1],b[2p+1][0],b[2p+1][1]}
    //          = {(n0,k8),(n0,k8+4),(n0+8,k8),(n0+8,k8+4)}
    const int rowB = (lane & 7) + (lane >> 4) * 8;
    const int colB = ((lane >> 3) & 1) * 4;

    const uint32_t aLane = (uint32_t)(((wm * 64 + rowA) * PITCH + colA) * 4);
    const uint32_t bLane = (uint32_t)((A_ST_FLOATS + (wn * 64 + rowB) * PITCH + colB) * 4);

    // cp.async issue helper: 3072 16B-segments per chunk (A:1024, B:2048)
    auto issue_chunk = [&](int ch) {
        float* stg = smem + (ch % NSTAGE) * STAGE_FLOATS;
        const int kof = ch * KC;
#pragma unroll
        for (int i = 0; i < 12; ++i) {
            const int u = tid + i * 256;
            const float* src;
            float* dst;
            if (u < 1024) {
                const int row = u >> 3, seg = u & 7;
                src = Abase + (size_t)row * Cc + kof + seg * 4;
                dst = stg + row * PITCH + seg * 4;
            } else {
                const int v = u - 1024;
                const int row = v >> 3, seg = v & 7;
                src = Bbase + (size_t)row * Cc + kof + seg * 4;
                dst = stg + A_ST_FLOATS + row * PITCH + seg * 4;
            }
            uint32_t daddr = (uint32_t)__cvta_generic_to_shared(dst);
            asm volatile("cp.async.cg.shared.global [%0], [%1], 16;"
                         :: "r"(daddr), "l"(src) : "memory");
        }
        asm volatile("cp.async.commit_group;" ::: "memory");
    };

    // Prologue: chunks 0,1
    issue_chunk(0);
    issue_chunk(1);

    float acc[4][8][4];
#pragma unroll
    for (int mt = 0; mt < 4; ++mt)
#pragma unroll
        for (int nt = 0; nt < 8; ++nt)
#pragma unroll
            for (int e = 0; e < 4; ++e) acc[mt][nt][e] = 0.f;

    uint32_t aR[2][4][4], bR[2][8][2];

#pragma unroll 1
    for (int ch = 0; ch < NCHK; ++ch) {
        if (ch < NCHK - 1) {
            asm volatile("cp.async.wait_group 1;" ::: "memory");
        } else {
            asm volatile("cp.async.wait_group 0;" ::: "memory");
        }
        __syncthreads();   // chunk ch visible to all; compute(ch-1) done by all

        if (ch + 2 < NCHK) issue_chunk(ch + 2);

        const uint32_t stS = smemS + (uint32_t)((ch % NSTAGE) * STAGE_FLOATS * 4);
        const uint32_t aBase = stS + aLane;
        const uint32_t bBase = stS + bLane;

        auto lfrag = [&](int ks, uint32_t (*a)[4], uint32_t (*b)[2]) {
            const uint32_t ko = (uint32_t)(ks * 8 * 4);
#pragma unroll
            for (int mt = 0; mt < 4; ++mt)
                ldsm_x4(a[mt], aBase + (uint32_t)(mt * 16 * PITCH * 4) + ko);
#pragma unroll
            for (int p = 0; p < 4; ++p)
                ldsm_x4(&b[2 * p][0], bBase + (uint32_t)(p * 16 * PITCH * 4) + ko);
        };

        lfrag(0, aR[0], bR[0]);
#pragma unroll
        for (int ks = 0; ks < 4; ++ks) {
            if (ks < 3) lfrag(ks + 1, aR[(ks + 1) & 1], bR[(ks + 1) & 1]);
#pragma unroll
            for (int mt = 0; mt < 4; ++mt)
#pragma unroll
                for (int nt = 0; nt < 8; ++nt)
                    mma_tf32(acc[mt][nt], aR[ks & 1][mt], bR[ks & 1][nt]);
        }
    }

    // Epilogue: bias + store
#pragma unroll
    for (int nt = 0; nt < 8; ++nt) {
        const int col = bn * BN + wn * 64 + nt * 8 + cq * 2;
        const float b0 = __ldg(bias + col);
        const float b1 = __ldg(bias + col + 1);
#pragma unroll
        for (int mt = 0; mt < 4; ++mt) {
            const size_t row0 = (size_t)(bm * BM + wm * 64 + mt * 16 + q);
            float2 v0, v1;
            v0.x = acc[mt][nt][0] + b0; v0.y = acc[mt][nt][1] + b1;
            v1.x = acc[mt][nt][2] + b0; v1.y = acc[mt][nt][3] + b1;
            *reinterpret_cast<float2*>(out + row0 * Cc + col) = v0;
            *reinterpret_cast<float2*>(out + (row0 + 8) * Cc + col) = v1;
        }
    }
}

// ---------------------------------------------------------------------------
extern "C" void kernel_launch(void* const* d_in, const int* in_sizes, int n_in,
                              void* d_out, int out_size)
{
    (void)in_sizes; (void)n_in; (void)out_size;
    const float* x    = (const float*)d_in[0];
    const float* logd = (const float*)d_in[1];
    const float* mixw = (const float*)d_in[2];
    const float* bias = (const float*)d_in[3];
    float* out = (float*)d_out;

    cudaFuncSetAttribute(gemm_mma_kernel, cudaFuncAttributeMaxDynamicSharedMemorySize,
                         SMEM_TOTAL);

    chunk_sum_kernel<<<Bb * NCHUNK, 128>>>(x, logd, mixw);
    apply_kernel<<<Bb * NCHUNK, 128>>>(x, logd);
    gemm_mma_kernel<<<512, 256, SMEM_TOTAL>>>(bias, out);
}

// round 8
// speedup vs baseline: 2.5666x; 1.1639x over previous
#include <cuda_runtime.h>
#include <cstdint>
#include <math.h>

// Problem dims
#define Bb 8
#define Tt 4096
#define Cc 512
#define NCHUNK 128
#define LCHUNK 32   // Tt / NCHUNK

// Scratch (device globals: no runtime allocation allowed)
__device__ __align__(256) float g_y[Bb * Tt * Cc];      // 64 MB intermediate y (tf32-rounded)
__device__ __align__(256) float g_A[Bb * NCHUNK * Cc];  // per-chunk weighted sums
__device__ __align__(256) float g_W[Cc * Cc];           // tf32-rounded weights

__device__ __forceinline__ float tf32_rn(float f) {
    uint32_t u;
    asm("cvt.rna.tf32.f32 %0, %1;" : "=r"(u) : "f"(f));
    return __uint_as_float(u);
}

// ---------------------------------------------------------------------------
// Kernel 1: per-chunk absolutely-weighted sums  A[b,k,c] = sum_j d^(t0+j) x
// First 512 blocks also convert one float4 of W to tf32 per thread.
// ---------------------------------------------------------------------------
__global__ void __launch_bounds__(128) chunk_sum_kernel(
    const float* __restrict__ x, const float* __restrict__ logd,
    const float* __restrict__ W)
{
    const int b = blockIdx.x / NCHUNK;
    const int k = blockIdx.x % NCHUNK;
    const int c = threadIdx.x * 4;

    // fused W tf32 conversion: 512 blocks * 128 threads * 4 = 262144 = Cc*Cc
    if (blockIdx.x < 512) {
        const int i = (blockIdx.x * 128 + threadIdx.x) * 4;
        float4 v = *reinterpret_cast<const float4*>(W + i);
        v.x = tf32_rn(v.x); v.y = tf32_rn(v.y); v.z = tf32_rn(v.z); v.w = tf32_rn(v.w);
        *reinterpret_cast<float4*>(&g_W[i]) = v;
    }

    float4 ld4 = *reinterpret_cast<const float4*>(logd + c);
    const float d0 = 1.0f / (1.0f + expf(-ld4.x));
    const float d1 = 1.0f / (1.0f + expf(-ld4.y));
    const float d2 = 1.0f / (1.0f + expf(-ld4.z));
    const float d3 = 1.0f / (1.0f + expf(-ld4.w));

    const float ft0 = (float)(k * LCHUNK);
    float w0 = exp2f(ft0 * log2f(d0));
    float w1 = exp2f(ft0 * log2f(d1));
    float w2 = exp2f(ft0 * log2f(d2));
    float w3 = exp2f(ft0 * log2f(d3));

    const float* xp = x + ((size_t)b * Tt + (size_t)k * LCHUNK) * Cc + c;

    float a0 = 0.f, a1 = 0.f, a2 = 0.f, a3 = 0.f;
#pragma unroll 8
    for (int j = 0; j < LCHUNK; ++j) {
        float4 v = *reinterpret_cast<const float4*>(xp + (size_t)j * Cc);
        a0 += w0 * v.x;
        a1 += w1 * v.y;
        a2 += w2 * v.z;
        a3 += w3 * v.w;
        w0 *= d0; w1 *= d1; w2 *= d2; w3 *= d3;
    }

    float4 r; r.x = a0; r.y = a1; r.z = a2; r.w = a3;
    *reinterpret_cast<float4*>(&g_A[((size_t)b * NCHUNK + k) * Cc + c]) = r;
}

// ---------------------------------------------------------------------------
// Kernel 2: prefix over chunks + local rescan; y = d^(T-1-t) * S, tf32-rounded
// ---------------------------------------------------------------------------
__global__ void __launch_bounds__(128) apply_kernel(
    const float* __restrict__ x, const float* __restrict__ logd)
{
    const int b = blockIdx.x / NCHUNK;
    const int k = blockIdx.x % NCHUNK;
    const int c = threadIdx.x * 4;

    float4 ld4 = *reinterpret_cast<const float4*>(logd + c);
    const float d0 = 1.0f / (1.0f + expf(-ld4.x));
    const float d1 = 1.0f / (1.0f + expf(-ld4.y));
    const float d2 = 1.0f / (1.0f + expf(-ld4.z));
    const float d3 = 1.0f / (1.0f + expf(-ld4.w));
    const float l20 = log2f(d0), l21 = log2f(d1), l22 = log2f(d2), l23 = log2f(d3);

    float P0 = 0.f, P1 = 0.f, P2 = 0.f, P3 = 0.f;
    const float* Aprow = g_A + (size_t)b * NCHUNK * Cc + c;
    for (int kk = 0; kk < k; ++kk) {
        float4 v = *reinterpret_cast<const float4*>(Aprow + (size_t)kk * Cc);
        P0 += v.x; P1 += v.y; P2 += v.z; P3 += v.w;
    }

    const int t0 = k * LCHUNK;
    const float ft0 = (float)t0;
    float w0 = exp2f(ft0 * l20);
    float w1 = exp2f(ft0 * l21);
    float w2 = exp2f(ft0 * l22);
    float w3 = exp2f(ft0 * l23);

    const float eb0 = (float)(Tt - 1 - t0) * l20;
    const float eb1 = (float)(Tt - 1 - t0) * l21;
    const float eb2 = (float)(Tt - 1 - t0) * l22;
    const float eb3 = (float)(Tt - 1 - t0) * l23;
    const float ee0 = (float)(Tt - 1 - t0 - (LCHUNK - 1)) * l20;
    const float ee1 = (float)(Tt - 1 - t0 - (LCHUNK - 1)) * l21;
    const float ee2 = (float)(Tt - 1 - t0 - (LCHUNK - 1)) * l22;
    const float ee3 = (float)(Tt - 1 - t0 - (LCHUNK - 1)) * l23;
    const bool ex0 = (eb0 < -100.f) && (ee0 > -140.f);
    const bool ex1 = (eb1 < -100.f) && (ee1 > -140.f);
    const bool ex2 = (eb2 < -100.f) && (ee2 > -140.f);
    const bool ex3 = (eb3 < -100.f) && (ee3 > -140.f);
    const bool anyex = ex0 | ex1 | ex2 | ex3;

    float pt0 = exp2f(eb0), pt1 = exp2f(eb1), pt2 = exp2f(eb2), pt3 = exp2f(eb3);
    const float i0 = 1.0f / d0, i1 = 1.0f / d1, i2 = 1.0f / d2, i3 = 1.0f / d3;

    float S0 = P0, S1 = P1, S2 = P2, S3 = P3;

    const float* xp = x + ((size_t)b * Tt + t0) * Cc + c;
    float* yp = g_y + ((size_t)b * Tt + t0) * Cc + c;

    if (!anyex) {
#pragma unroll 4
        for (int j = 0; j < LCHUNK; ++j) {
            float4 v = *reinterpret_cast<const float4*>(xp + (size_t)j * Cc);
            S0 += w0 * v.x; w0 *= d0;
            S1 += w1 * v.y; w1 *= d1;
            S2 += w2 * v.z; w2 *= d2;
            S3 += w3 * v.w; w3 *= d3;
            float4 r;
            r.x = tf32_rn(pt0 * S0); r.y = tf32_rn(pt1 * S1);
            r.z = tf32_rn(pt2 * S2); r.w = tf32_rn(pt3 * S3);
            pt0 *= i0; pt1 *= i1; pt2 *= i2; pt3 *= i3;
            *reinterpret_cast<float4*>(yp + (size_t)j * Cc) = r;
        }
    } else {
        for (int j = 0; j < LCHUNK; ++j) {
            const float tj = (float)(Tt - 1 - t0 - j);
            pt0 = ex0 ? exp2f(tj * l20) : pt0;
            pt1 = ex1 ? exp2f(tj * l21) : pt1;
            pt2 = ex2 ? exp2f(tj * l22) : pt2;
            pt3 = ex3 ? exp2f(tj * l23) : pt3;
            float4 v = *reinterpret_cast<const float4*>(xp + (size_t)j * Cc);
            S0 += w0 * v.x; w0 *= d0;
            S1 += w1 * v.y; w1 *= d1;
            S2 += w2 * v.z; w2 *= d2;
            S3 += w3 * v.w; w3 *= d3;
            float4 r;
            r.x = tf32_rn(pt0 * S0); r.y = tf32_rn(pt1 * S1);
            r.z = tf32_rn(pt2 * S2); r.w = tf32_rn(pt3 * S3);
            pt0 = ex0 ? pt0 : pt0 * i0;
            pt1 = ex1 ? pt1 : pt1 * i1;
            pt2 = ex2 ? pt2 : pt2 * i2;
            pt3 = ex3 ? pt3 : pt3 * i3;
            *reinterpret_cast<float4*>(yp + (size_t)j * Cc) = r;
        }
    }
}

// ---------------------------------------------------------------------------
// Kernel 3: tf32 tensor-core GEMM via mma.sync + ldmatrix.
// out = y @ W^T + bias. CTA tile 128x256x32, 512 threads (16 warps 4m x 4n,
// warp tile 32x64), 3-stage cp.async pipeline, LDSM.x4 fragment loads,
// pitch 36 floats (conflict-free).
// ---------------------------------------------------------------------------
#define BM 128
#define BN 256
#define KC 32
#define NCHK (Cc / KC)           // 16
#define PITCH 36                 // floats per smem row
#define A_ST_FLOATS (BM * PITCH) // 4608
#define B_ST_FLOATS (BN * PITCH) // 9216
#define STAGE_FLOATS (A_ST_FLOATS + B_ST_FLOATS)  // 13824
#define NSTAGE 3
#define SMEM_TOTAL (NSTAGE * STAGE_FLOATS * 4)    // 165888 B

__device__ __forceinline__ void mma_tf32(float* d, const uint32_t* a, const uint32_t* b) {
    asm volatile(
        "mma.sync.aligned.m16n8k8.row.col.f32.tf32.tf32.f32 "
        "{%0,%1,%2,%3}, {%4,%5,%6,%7}, {%8,%9}, {%0,%1,%2,%3};"
        : "+f"(d[0]), "+f"(d[1]), "+f"(d[2]), "+f"(d[3])
        : "r"(a[0]), "r"(a[1]), "r"(a[2]), "r"(a[3]), "r"(b[0]), "r"(b[1]));
}

__device__ __forceinline__ void ldsm_x4(uint32_t* r, uint32_t saddr) {
    asm volatile(
        "ldmatrix.sync.aligned.m8n8.x4.shared.b16 {%0,%1,%2,%3}, [%4];"
        : "=r"(r[0]), "=r"(r[1]), "=r"(r[2]), "=r"(r[3]) : "r"(saddr));
}

__global__ void __launch_bounds__(512, 1) gemm_mma_kernel(
    const float* __restrict__ bias, float* __restrict__ out)
{
    extern __shared__ __align__(128) float smem[];

    const int tid = threadIdx.x;
    const int wid = tid >> 5;
    const int lane = tid & 31;
    const int q = lane >> 2;   // 0..7
    const int cq = lane & 3;   // 0..3

    const int bm = blockIdx.x >> 1;   // 0..255
    const int bn = blockIdx.x & 1;    // 0..1
    const int wm = wid >> 2;          // 0..3  (32-row blocks)
    const int wn = wid & 3;           // 0..3  (64-col blocks)

    const float* Abase = g_y + (size_t)(bm * BM) * Cc;
    const float* Bbase = g_W + (size_t)(bn * BN) * Cc;

    const uint32_t smemS = (uint32_t)__cvta_generic_to_shared(smem);

    // ldmatrix per-lane addresses (A: {(m0,k8),(m0+8,k8),(m0,k8+4),(m0+8,k8+4)};
    //  B pair p: {(n0,k8),(n0,k8+4),(n0+8,k8),(n0+8,k8+4)})
    const int rowA = (lane & 7) + ((lane >> 3) & 1) * 8;
    const int colA = (lane >> 4) * 4;
    const int rowB = (lane & 7) + (lane >> 4) * 8;
    const int colB = ((lane >> 3) & 1) * 4;

    const uint32_t aLane = (uint32_t)(((wm * 32 + rowA) * PITCH + colA) * 4);
    const uint32_t bLane = (uint32_t)((A_ST_FLOATS + (wn * 64 + rowB) * PITCH + colB) * 4);

    // cp.async issue helper: 3072 16B-segments per chunk (A:1024, B:2048)
    auto issue_chunk = [&](int ch) {
        float* stg = smem + (ch % NSTAGE) * STAGE_FLOATS;
        const int kof = ch * KC;
#pragma unroll
        for (int i = 0; i < 6; ++i) {
            const int u = tid + i * 512;
            const float* src;
            float* dst;
            if (u < 1024) {
                const int row = u >> 3, seg = u & 7;
                src = Abase + (size_t)row * Cc + kof + seg * 4;
                dst = stg + row * PITCH + seg * 4;
            } else {
                const int v = u - 1024;
                const int row = v >> 3, seg = v & 7;
                src = Bbase + (size_t)row * Cc + kof + seg * 4;
                dst = stg + A_ST_FLOATS + row * PITCH + seg * 4;
            }
            uint32_t daddr = (uint32_t)__cvta_generic_to_shared(dst);
            asm volatile("cp.async.cg.shared.global [%0], [%1], 16;"
                         :: "r"(daddr), "l"(src) : "memory");
        }
        asm volatile("cp.async.commit_group;" ::: "memory");
    };

    // Prologue: chunks 0,1
    issue_chunk(0);
    issue_chunk(1);

    float acc[2][8][4];
#pragma unroll
    for (int mt = 0; mt < 2; ++mt)
#pragma unroll
        for (int nt = 0; nt < 8; ++nt)
#pragma unroll
            for (int e = 0; e < 4; ++e) acc[mt][nt][e] = 0.f;

#pragma unroll 1
    for (int ch = 0; ch < NCHK; ++ch) {
        if (ch < NCHK - 1) {
            asm volatile("cp.async.wait_group 1;" ::: "memory");
        } else {
            asm volatile("cp.async.wait_group 0;" ::: "memory");
        }
        __syncthreads();   // chunk ch visible; compute(ch-1) done by all

        if (ch + 2 < NCHK) issue_chunk(ch + 2);

        const uint32_t stS = smemS + (uint32_t)((ch % NSTAGE) * STAGE_FLOATS * 4);
        const uint32_t aBase = stS + aLane;
        const uint32_t bBase = stS + bLane;

#pragma unroll
        for (int ks = 0; ks < 4; ++ks) {
            const uint32_t ko = (uint32_t)(ks * 8 * 4);
            uint32_t a[2][4], b[8][2];
#pragma unroll
            for (int mt = 0; mt < 2; ++mt)
                ldsm_x4(a[mt], aBase + (uint32_t)(mt * 16 * PITCH * 4) + ko);
#pragma unroll
            for (int p = 0; p < 4; ++p)
                ldsm_x4(&b[2 * p][0], bBase + (uint32_t)(p * 16 * PITCH * 4) + ko);
#pragma unroll
            for (int mt = 0; mt < 2; ++mt)
#pragma unroll
                for (int nt = 0; nt < 8; ++nt)
                    mma_tf32(acc[mt][nt], a[mt], b[nt]);
        }
    }

    // Epilogue: bias + store
#pragma unroll
    for (int nt = 0; nt < 8; ++nt) {
        const int col = bn * BN + wn * 64 + nt * 8 + cq * 2;
        const float b0 = __ldg(bias + col);
        const float b1 = __ldg(bias + col + 1);
#pragma unroll
        for (int mt = 0; mt < 2; ++mt) {
            const size_t row0 = (size_t)(bm * BM + wm * 32 + mt * 16 + q);
            float2 v0, v1;
            v0.x = acc[mt][nt][0] + b0; v0.y = acc[mt][nt][1] + b1;
            v1.x = acc[mt][nt][2] + b0; v1.y = acc[mt][nt][3] + b1;
            *reinterpret_cast<float2*>(out + row0 * Cc + col) = v0;
            *reinterpret_cast<float2*>(out + (row0 + 8) * Cc + col) = v1;
        }
    }
}

// ---------------------------------------------------------------------------
extern "C" void kernel_launch(void* const* d_in, const int* in_sizes, int n_in,
                              void* d_out, int out_size)
{
    (void)in_sizes; (void)n_in; (void)out_size;
    const float* x    = (const float*)d_in[0];
    const float* logd = (const float*)d_in[1];
    const float* mixw = (const float*)d_in[2];
    const float* bias = (const float*)d_in[3];
    float* out = (float*)d_out;

    cudaFuncSetAttribute(gemm_mma_kernel, cudaFuncAttributeMaxDynamicSharedMemorySize,
                         SMEM_TOTAL);

    chunk_sum_kernel<<<Bb * NCHUNK, 128>>>(x, logd, mixw);
    apply_kernel<<<Bb * NCHUNK, 128>>>(x, logd);
    gemm_mma_kernel<<<512, 512, SMEM_TOTAL>>>(bias, out);
}

// round 9
// speedup vs baseline: 2.8897x; 1.1259x over previous
#include <cuda_runtime.h>
#include <cstdint>
#include <math.h>

// Problem dims
#define Bb 8
#define Tt 4096
#define Cc 512
#define NCHUNK 128
#define LCHUNK 32   // Tt / NCHUNK

// Scratch (device globals: no runtime allocation allowed)
__device__ __align__(256) float g_y[Bb * Tt * Cc];      // 64 MB intermediate y (tf32-rounded)
__device__ __align__(256) float g_A[Bb * NCHUNK * Cc];  // chunk sums -> exclusive prefix
__device__ __align__(256) float g_W[Cc * Cc];           // tf32-rounded weights

__device__ __forceinline__ float tf32_rn(float f) {
    uint32_t u;
    asm("cvt.rna.tf32.f32 %0, %1;" : "=r"(u) : "f"(f));
    return __uint_as_float(u);
}

// ---------------------------------------------------------------------------
// Kernel 1: per-chunk absolutely-weighted sums  A[b,k,c] = sum_j d^(t0+j) x
// First 512 blocks also convert one float4 of W to tf32 per thread.
// ---------------------------------------------------------------------------
__global__ void __launch_bounds__(128) chunk_sum_kernel(
    const float* __restrict__ x, const float* __restrict__ logd,
    const float* __restrict__ W)
{
    const int b = blockIdx.x / NCHUNK;
    const int k = blockIdx.x % NCHUNK;
    const int c = threadIdx.x * 4;

    if (blockIdx.x < 512) {
        const int i = (blockIdx.x * 128 + threadIdx.x) * 4;
        float4 v = *reinterpret_cast<const float4*>(W + i);
        v.x = tf32_rn(v.x); v.y = tf32_rn(v.y); v.z = tf32_rn(v.z); v.w = tf32_rn(v.w);
        *reinterpret_cast<float4*>(&g_W[i]) = v;
    }

    float4 ld4 = *reinterpret_cast<const float4*>(logd + c);
    const float d0 = 1.0f / (1.0f + expf(-ld4.x));
    const float d1 = 1.0f / (1.0f + expf(-ld4.y));
    const float d2 = 1.0f / (1.0f + expf(-ld4.z));
    const float d3 = 1.0f / (1.0f + expf(-ld4.w));

    const float ft0 = (float)(k * LCHUNK);
    float w0 = exp2f(ft0 * log2f(d0));
    float w1 = exp2f(ft0 * log2f(d1));
    float w2 = exp2f(ft0 * log2f(d2));
    float w3 = exp2f(ft0 * log2f(d3));

    const float* xp = x + ((size_t)b * Tt + (size_t)k * LCHUNK) * Cc + c;

    float a0 = 0.f, a1 = 0.f, a2 = 0.f, a3 = 0.f;
#pragma unroll 8
    for (int j = 0; j < LCHUNK; ++j) {
        float4 v = *reinterpret_cast<const float4*>(xp + (size_t)j * Cc);
        a0 += w0 * v.x;
        a1 += w1 * v.y;
        a2 += w2 * v.z;
        a3 += w3 * v.w;
        w0 *= d0; w1 *= d1; w2 *= d2; w3 *= d3;
    }

    float4 r; r.x = a0; r.y = a1; r.z = a2; r.w = a3;
    *reinterpret_cast<float4*>(&g_A[((size_t)b * NCHUNK + k) * Cc + c]) = r;
}

// ---------------------------------------------------------------------------
// Kernel 1b: in-place exclusive prefix over chunks of g_A.
// One thread per (b,c): serial cumsum over k (same add order as before).
// ---------------------------------------------------------------------------
__global__ void __launch_bounds__(128) prefix_kernel()
{
    const int gid = blockIdx.x * 128 + threadIdx.x;  // 0..4095
    const int b = gid >> 9;
    const int c = gid & 511;
    float* Ap = g_A + (size_t)b * NCHUNK * Cc + c;
    float P = 0.f;
#pragma unroll 8
    for (int k = 0; k < NCHUNK; ++k) {
        const float v = Ap[(size_t)k * Cc];
        Ap[(size_t)k * Cc] = P;
        P += v;
    }
}

// ---------------------------------------------------------------------------
// Kernel 2: local rescan; y = d^(T-1-t) * (P + local sum), tf32-rounded.
// P comes from the exclusive-prefix g_A row.
// ---------------------------------------------------------------------------
__global__ void __launch_bounds__(128) apply_kernel(
    const float* __restrict__ x, const float* __restrict__ logd)
{
    const int b = blockIdx.x / NCHUNK;
    const int k = blockIdx.x % NCHUNK;
    const int c = threadIdx.x * 4;

    float4 ld4 = *reinterpret_cast<const float4*>(logd + c);
    const float d0 = 1.0f / (1.0f + expf(-ld4.x));
    const float d1 = 1.0f / (1.0f + expf(-ld4.y));
    const float d2 = 1.0f / (1.0f + expf(-ld4.z));
    const float d3 = 1.0f / (1.0f + expf(-ld4.w));
    const float l20 = log2f(d0), l21 = log2f(d1), l22 = log2f(d2), l23 = log2f(d3);

    const float4 Pv = *reinterpret_cast<const float4*>(
        g_A + ((size_t)b * NCHUNK + k) * Cc + c);

    const int t0 = k * LCHUNK;
    const float ft0 = (float)t0;
    float w0 = exp2f(ft0 * l20);
    float w1 = exp2f(ft0 * l21);
    float w2 = exp2f(ft0 * l22);
    float w3 = exp2f(ft0 * l23);

    const float eb0 = (float)(Tt - 1 - t0) * l20;
    const float eb1 = (float)(Tt - 1 - t0) * l21;
    const float eb2 = (float)(Tt - 1 - t0) * l22;
    const float eb3 = (float)(Tt - 1 - t0) * l23;
    const float ee0 = (float)(Tt - 1 - t0 - (LCHUNK - 1)) * l20;
    const float ee1 = (float)(Tt - 1 - t0 - (LCHUNK - 1)) * l21;
    const float ee2 = (float)(Tt - 1 - t0 - (LCHUNK - 1)) * l22;
    const float ee3 = (float)(Tt - 1 - t0 - (LCHUNK - 1)) * l23;
    const bool ex0 = (eb0 < -100.f) && (ee0 > -140.f);
    const bool ex1 = (eb1 < -100.f) && (ee1 > -140.f);
    const bool ex2 = (eb2 < -100.f) && (ee2 > -140.f);
    const bool ex3 = (eb3 < -100.f) && (ee3 > -140.f);
    const bool anyex = ex0 | ex1 | ex2 | ex3;

    float pt0 = exp2f(eb0), pt1 = exp2f(eb1), pt2 = exp2f(eb2), pt3 = exp2f(eb3);
    const float i0 = 1.0f / d0, i1 = 1.0f / d1, i2 = 1.0f / d2, i3 = 1.0f / d3;

    float S0 = Pv.x, S1 = Pv.y, S2 = Pv.z, S3 = Pv.w;

    const float* xp = x + ((size_t)b * Tt + t0) * Cc + c;
    float* yp = g_y + ((size_t)b * Tt + t0) * Cc + c;

    if (!anyex) {
#pragma unroll 4
        for (int j = 0; j < LCHUNK; ++j) {
            float4 v = *reinterpret_cast<const float4*>(xp + (size_t)j * Cc);
            S0 += w0 * v.x; w0 *= d0;
            S1 += w1 * v.y; w1 *= d1;
            S2 += w2 * v.z; w2 *= d2;
            S3 += w3 * v.w; w3 *= d3;
            float4 r;
            r.x = tf32_rn(pt0 * S0); r.y = tf32_rn(pt1 * S1);
            r.z = tf32_rn(pt2 * S2); r.w = tf32_rn(pt3 * S3);
            pt0 *= i0; pt1 *= i1; pt2 *= i2; pt3 *= i3;
            *reinterpret_cast<float4*>(yp + (size_t)j * Cc) = r;
        }
    } else {
        for (int j = 0; j < LCHUNK; ++j) {
            const float tj = (float)(Tt - 1 - t0 - j);
            pt0 = ex0 ? exp2f(tj * l20) : pt0;
            pt1 = ex1 ? exp2f(tj * l21) : pt1;
            pt2 = ex2 ? exp2f(tj * l22) : pt2;
            pt3 = ex3 ? exp2f(tj * l23) : pt3;
            float4 v = *reinterpret_cast<const float4*>(xp + (size_t)j * Cc);
            S0 += w0 * v.x; w0 *= d0;
            S1 += w1 * v.y; w1 *= d1;
            S2 += w2 * v.z; w2 *= d2;
            S3 += w3 * v.w; w3 *= d3;
            float4 r;
            r.x = tf32_rn(pt0 * S0); r.y = tf32_rn(pt1 * S1);
            r.z = tf32_rn(pt2 * S2); r.w = tf32_rn(pt3 * S3);
            pt0 = ex0 ? pt0 : pt0 * i0;
            pt1 = ex1 ? pt1 : pt1 * i1;
            pt2 = ex2 ? pt2 : pt2 * i2;
            pt3 = ex3 ? pt3 : pt3 * i3;
            *reinterpret_cast<float4*>(yp + (size_t)j * Cc) = r;
        }
    }
}

// ---------------------------------------------------------------------------
// Kernel 3: tf32 tensor-core GEMM via mma.sync + ldmatrix.
// out = y @ W^T + bias. CTA tile 128x128x32, 256 threads (8 warps 4m x 2n,
// warp tile 32x64), 2 CTAs/SM, 3-stage cp.async pipeline, LDSM.x4 loads,
// pitch 36 floats (conflict-free).
// ---------------------------------------------------------------------------
#define BM 128
#define BN 128
#define KC 32
#define NCHK (Cc / KC)           // 16
#define PITCH 36                 // floats per smem row
#define A_ST_FLOATS (BM * PITCH) // 4608
#define B_ST_FLOATS (BN * PITCH) // 4608
#define STAGE_FLOATS (A_ST_FLOATS + B_ST_FLOATS)  // 9216
#define NSTAGE 3
#define SMEM_TOTAL (NSTAGE * STAGE_FLOATS * 4)    // 110592 B

__device__ __forceinline__ void mma_tf32(float* d, const uint32_t* a, const uint32_t* b) {
    asm volatile(
        "mma.sync.aligned.m16n8k8.row.col.f32.tf32.tf32.f32 "
        "{%0,%1,%2,%3}, {%4,%5,%6,%7}, {%8,%9}, {%0,%1,%2,%3};"
        : "+f"(d[0]), "+f"(d[1]), "+f"(d[2]), "+f"(d[3])
        : "r"(a[0]), "r"(a[1]), "r"(a[2]), "r"(a[3]), "r"(b[0]), "r"(b[1]));
}

__device__ __forceinline__ void ldsm_x4(uint32_t* r, uint32_t saddr) {
    asm volatile(
        "ldmatrix.sync.aligned.m8n8.x4.shared.b16 {%0,%1,%2,%3}, [%4];"
        : "=r"(r[0]), "=r"(r[1]), "=r"(r[2]), "=r"(r[3]) : "r"(saddr));
}

__global__ void __launch_bounds__(256, 2) gemm_mma_kernel(
    const float* __restrict__ bias, float* __restrict__ out)
{
    extern __shared__ __align__(128) float smem[];

    const int tid = threadIdx.x;
    const int wid = tid >> 5;
    const int lane = tid & 31;
    const int q = lane >> 2;   // 0..7
    const int cq = lane & 3;   // 0..3

    const int bm = blockIdx.x >> 2;   // 0..255
    const int bn = blockIdx.x & 3;    // 0..3
    const int wm = wid >> 1;          // 0..3  (32-row blocks)
    const int wn = wid & 1;           // 0..1  (64-col blocks)

    const float* Abase = g_y + (size_t)(bm * BM) * Cc;
    const float* Bbase = g_W + (size_t)(bn * BN) * Cc;

    const uint32_t smemS = (uint32_t)__cvta_generic_to_shared(smem);

    // ldmatrix per-lane addresses (A: {(m0,k8),(m0+8,k8),(m0,k8+4),(m0+8,k8+4)};
    //  B pair p: {(n0,k8),(n0,k8+4),(n0+8,k8),(n0+8,k8+4)})
    const int rowA = (lane & 7) + ((lane >> 3) & 1) * 8;
    const int colA = (lane >> 4) * 4;
    const int rowB = (lane & 7) + (lane >> 4) * 8;
    const int colB = ((lane >> 3) & 1) * 4;

    const uint32_t aLane = (uint32_t)(((wm * 32 + rowA) * PITCH + colA) * 4);
    const uint32_t bLane = (uint32_t)((A_ST_FLOATS + (wn * 64 + rowB) * PITCH + colB) * 4);

    // cp.async issue helper: 2048 16B-segments per chunk (A:1024, B:1024)
    auto issue_chunk = [&](int ch) {
        float* stg = smem + (ch % NSTAGE) * STAGE_FLOATS;
        const int kof = ch * KC;
#pragma unroll
        for (int i = 0; i < 8; ++i) {
            const int u = tid + i * 256;
            const float* src;
            float* dst;
            if (u < 1024) {
                const int row = u >> 3, seg = u & 7;
                src = Abase + (size_t)row * Cc + kof + seg * 4;
                dst = stg + row * PITCH + seg * 4;
            } else {
                const int v = u - 1024;
                const int row = v >> 3, seg = v & 7;
                src = Bbase + (size_t)row * Cc + kof + seg * 4;
                dst = stg + A_ST_FLOATS + row * PITCH + seg * 4;
            }
            uint32_t daddr = (uint32_t)__cvta_generic_to_shared(dst);
            asm volatile("cp.async.cg.shared.global [%0], [%1], 16;"
                         :: "r"(daddr), "l"(src) : "memory");
        }
        asm volatile("cp.async.commit_group;" ::: "memory");
    };

    // Prologue: chunks 0,1
    issue_chunk(0);
    issue_chunk(1);

    float acc[2][8][4];
#pragma unroll
    for (int mt = 0; mt < 2; ++mt)
#pragma unroll
        for (int nt = 0; nt < 8; ++nt)
#pragma unroll
            for (int e = 0; e < 4; ++e) acc[mt][nt][e] = 0.f;

#pragma unroll 1
    for (int ch = 0; ch < NCHK; ++ch) {
        if (ch < NCHK - 1) {
            asm volatile("cp.async.wait_group 1;" ::: "memory");
        } else {
            asm volatile("cp.async.wait_group 0;" ::: "memory");
        }
        __syncthreads();   // chunk ch visible; compute(ch-1) done by all

        if (ch + 2 < NCHK) issue_chunk(ch + 2);

        const uint32_t stS = smemS + (uint32_t)((ch % NSTAGE) * STAGE_FLOATS * 4);
        const uint32_t aBase = stS + aLane;
        const uint32_t bBase = stS + bLane;

#pragma unroll
        for (int ks = 0; ks < 4; ++ks) {
            const uint32_t ko = (uint32_t)(ks * 8 * 4);
            uint32_t a[2][4], b[8][2];
#pragma unroll
            for (int mt = 0; mt < 2; ++mt)
                ldsm_x4(a[mt], aBase + (uint32_t)(mt * 16 * PITCH * 4) + ko);
#pragma unroll
            for (int p = 0; p < 4; ++p)
                ldsm_x4(&b[2 * p][0], bBase + (uint32_t)(p * 16 * PITCH * 4) + ko);
#pragma unroll
            for (int mt = 0; mt < 2; ++mt)
#pragma unroll
                for (int nt = 0; nt < 8; ++nt)
                    mma_tf32(acc[mt][nt], a[mt], b[nt]);
        }
    }

    // Epilogue: bias + store
#pragma unroll
    for (int nt = 0; nt < 8; ++nt) {
        const int col = bn * BN + wn * 64 + nt * 8 + cq * 2;
        const float b0 = __ldg(bias + col);
        const float b1 = __ldg(bias + col + 1);
#pragma unroll
        for (int mt = 0; mt < 2; ++mt) {
            const size_t row0 = (size_t)(bm * BM + wm * 32 + mt * 16 + q);
            float2 v0, v1;
            v0.x = acc[mt][nt][0] + b0; v0.y = acc[mt][nt][1] + b1;
            v1.x = acc[mt][nt][2] + b0; v1.y = acc[mt][nt][3] + b1;
            *reinterpret_cast<float2*>(out + row0 * Cc + col) = v0;
            *reinterpret_cast<float2*>(out + (row0 + 8) * Cc + col) = v1;
        }
    }
}

// ---------------------------------------------------------------------------
extern "C" void kernel_launch(void* const* d_in, const int* in_sizes, int n_in,
                              void* d_out, int out_size)
{
    (void)in_sizes; (void)n_in; (void)out_size;
    const float* x    = (const float*)d_in[0];
    const float* logd = (const float*)d_in[1];
    const float* mixw = (const float*)d_in[2];
    const float* bias = (const float*)d_in[3];
    float* out = (float*)d_out;

    cudaFuncSetAttribute(gemm_mma_kernel, cudaFuncAttributeMaxDynamicSharedMemorySize,
                         SMEM_TOTAL);

    chunk_sum_kernel<<<Bb * NCHUNK, 128>>>(x, logd, mixw);
    prefix_kernel<<<32, 128>>>();
    apply_kernel<<<Bb * NCHUNK, 128>>>(x, logd);
    gemm_mma_kernel<<<1024, 256, SMEM_TOTAL>>>(bias, out);
}